// round 8
// baseline (speedup 1.0000x reference)
#include <cuda_runtime.h>
#include <cuda_fp16.h>

#define NN 100000
#define EE 1600000
#define TPB 256
#define SCANB 391          // ceil(NN/256)

typedef unsigned long long u64;

// ---- scratch (__device__ globals; no allocations allowed) ----
__device__ __half   g_xlh[NN * 64];   // fp16 x @ Wl + bl
__device__ __half   g_xrh[NN * 64];   // fp16 x @ Wr + br
__device__ float4   g_a4[EE];         // per-edge exp(alpha) per head
__device__ float    g_gate[EE];       // per-edge gate
__device__ int2     g_sed[EE];        // CSR-sorted {src, eid}
__device__ int      g_cnt[NN];        // degree histogram
__device__ int      g_loc[NN];        // block-local exclusive scan
__device__ int      g_bsum[512];      // per-block sums (padded)
__device__ int      g_boff[512];      // scanned block offsets
__device__ int      g_off[NN + 1];    // CSR row offsets
__device__ int      g_cur[NN];        // scatter cursors

// ---- small params in constant memory (uniform-address use only) ----
__constant__ __align__(16) float cWe[1024];   // [16,64]
__constant__ __align__(16) float cWg1[512];   // [16,32]
__constant__ __align__(16) float cWg2[32];
__constant__ __align__(16) float cbg1[32];
__constant__ __align__(16) float catt[64];
__constant__ float cbg2[1];

__device__ __forceinline__ float sigmoidf_(float v) {
    return 1.f / (1.f + __expf(-v));
}
__device__ __forceinline__ u64 pack2(float lo, float hi) {
    u64 r; asm("mov.b64 %0, {%1,%2};" : "=l"(r) : "f"(lo), "f"(hi)); return r;
}
__device__ __forceinline__ void unpack2(u64 v, float& lo, float& hi) {
    asm("mov.b64 {%0,%1}, %2;" : "=f"(lo), "=f"(hi) : "l"(v));
}
__device__ __forceinline__ void fma2(u64& d, u64 a, u64 b) {
    asm("fma.rn.f32x2 %0, %1, %2, %0;" : "+l"(d) : "l"(a), "l"(b));
}
__device__ __forceinline__ float leaky(float m) { return fmaxf(m, 0.2f * m); }
__device__ __forceinline__ void cpa16(__half* smem_dst, const __half* gsrc) {
    unsigned d = (unsigned)__cvta_generic_to_shared(smem_dst);
    asm volatile("cp.async.ca.shared.global [%0], [%1], 16;"
                 :: "r"(d), "l"(gsrc) : "memory");
}
__device__ __forceinline__ unsigned h2_bits(__half2 v) {
    return *reinterpret_cast<unsigned*>(&v);
}

// ---------------------------------------------------------------------------
// Kernel 1: node transforms (fp16 out) + zero degree counters.
// ---------------------------------------------------------------------------
__global__ void __launch_bounds__(256) k_prep(
        const float* __restrict__ x,
        const float* __restrict__ Wl, const float* __restrict__ bl,
        const float* __restrict__ Wr, const float* __restrict__ br) {
    __shared__ __align__(16) float Ws[64 * 128];
    __shared__ __align__(16) float xs[64 * 64];
    int t = threadIdx.x;
    int nb = blockIdx.x * 64;

#pragma unroll
    for (int i = 0; i < 16; i++) {
        int idx = t + i * 256;
        int k = idx >> 6, c = idx & 63;
        Ws[k * 128 + c]      = Wl[idx];
        Ws[k * 128 + 64 + c] = Wr[idx];
    }
#pragma unroll
    for (int i = 0; i < 16; i++) {
        int idx = t + i * 256;
        int n = nb + (idx >> 6);
        xs[idx] = (n < NN) ? x[(size_t)n * 64 + (idx & 63)] : 0.f;
    }
    if (t < 64 && nb + t < NN) g_cnt[nb + t] = 0;
    __syncthreads();

    int cg = t & 31, ng = t >> 5;
    int c0 = cg * 4;
    const float* bsrc = (c0 < 64) ? (bl + c0) : (br + (c0 - 64));
    float4 bias = *(const float4*)bsrc;

    u64 acc[8][2];
#pragma unroll
    for (int j = 0; j < 8; j++) {
        acc[j][0] = pack2(bias.x, bias.y);
        acc[j][1] = pack2(bias.z, bias.w);
    }

    for (int k4 = 0; k4 < 16; k4++) {
        float4 xv[8];
#pragma unroll
        for (int j = 0; j < 8; j++)
            xv[j] = *(const float4*)&xs[(ng * 8 + j) * 64 + k4 * 4];
#pragma unroll
        for (int kk = 0; kk < 4; kk++) {
            float4 wv = *(const float4*)&Ws[(k4 * 4 + kk) * 128 + c0];
            u64 w01 = pack2(wv.x, wv.y), w23 = pack2(wv.z, wv.w);
#pragma unroll
            for (int j = 0; j < 8; j++) {
                float xsc = (kk == 0) ? xv[j].x : (kk == 1) ? xv[j].y
                          : (kk == 2) ? xv[j].z : xv[j].w;
                u64 xx = pack2(xsc, xsc);
                fma2(acc[j][0], xx, w01);
                fma2(acc[j][1], xx, w23);
            }
        }
    }

    __half* dsth = (c0 < 64) ? g_xlh : g_xrh;
    int cc = c0 & 63;
#pragma unroll
    for (int j = 0; j < 8; j++) {
        int n = nb + ng * 8 + j;
        if (n < NN) {
            float o0, o1, o2, o3;
            unpack2(acc[j][0], o0, o1);
            unpack2(acc[j][1], o2, o3);
            uint2 p;
            p.x = h2_bits(__floats2half2_rn(o0, o1));
            p.y = h2_bits(__floats2half2_rn(o2, o3));
            *(uint2*)&dsth[(size_t)n * 64 + cc] = p;
        }
    }
}

// ---------------------------------------------------------------------------
// CSR construction: histogram -> scan (3 small kernels) -> scatter
// ---------------------------------------------------------------------------
__global__ void k_hist(const int* __restrict__ ei) {
    int e = blockIdx.x * blockDim.x + threadIdx.x;
    atomicAdd(&g_cnt[ei[EE + e]], 1);
}

__global__ void k_scanA() {                 // per-block exclusive scan of g_cnt
    __shared__ int s[256];
    int t = threadIdx.x;
    int n = blockIdx.x * 256 + t;
    int v = (n < NN) ? g_cnt[n] : 0;
    s[t] = v;
    __syncthreads();
#pragma unroll
    for (int o = 1; o < 256; o <<= 1) {
        int u = (t >= o) ? s[t - o] : 0;
        __syncthreads();
        s[t] += u;
        __syncthreads();
    }
    if (n < NN) g_loc[n] = s[t] - v;
    if (t == 255) g_bsum[blockIdx.x] = s[255];
}

__global__ void k_scanB() {                 // scan of block sums (1 block)
    __shared__ int s[512];
    int t = threadIdx.x;
    int v = (t < SCANB) ? g_bsum[t] : 0;
    s[t] = v;
    __syncthreads();
#pragma unroll
    for (int o = 1; o < 512; o <<= 1) {
        int u = (t >= o) ? s[t - o] : 0;
        __syncthreads();
        s[t] += u;
        __syncthreads();
    }
    g_boff[t] = s[t] - v;
}

__global__ void k_scanC() {                 // combine + init cursors
    int n = blockIdx.x * 256 + threadIdx.x;
    if (n < NN) {
        int o = g_loc[n] + g_boff[blockIdx.x];
        g_off[n] = o;
        g_cur[n] = o;
    }
    if (n == 0) g_off[NN] = EE;
}

__global__ void k_scatter(const int* __restrict__ ei) {
    int e = blockIdx.x * blockDim.x + threadIdx.x;
    int src = ei[e];
    int tgt = ei[EE + e];
    int p = atomicAdd(&g_cur[tgt], 1);
    g_sed[p] = make_int2(src, e);
}

// ---------------------------------------------------------------------------
// Kernel: fused edge pass (NO atomics, NO scatter). Stores a4 + gate
// coalesced per edge. 128 thr / 4 warps, fp16 row staging.
// ---------------------------------------------------------------------------
#define ETPB 128
#define RST 72

__global__ void __launch_bounds__(ETPB, 6) k_edge(
        const int* __restrict__ ei, const float* __restrict__ eag) {
    __shared__ __align__(16) __half sXL[4][32 * RST];
    __shared__ __align__(16) __half sXR[4][32 * RST];

    int t = threadIdx.x, lane = t & 31, w = t >> 5;
    __half* XL = sXL[w];
    __half* XR = sXR[w];

    int e = blockIdx.x * ETPB + t;
    int src = ei[e];
    int tgt = ei[EE + e];
    (void)tgt;

    int rlane = lane >> 3;
    int off8  = (lane & 7) * 8;
#pragma unroll
    for (int i = 0; i < 8; i++) {
        int r  = i * 4 + rlane;
        int s  = __shfl_sync(0xFFFFFFFFu, src, r);
        int tg = __shfl_sync(0xFFFFFFFFu,
                             ei[EE + blockIdx.x * ETPB + w * 32 + r], 0);
        // (tg shuffled below properly; see note) -- replaced by direct shfl:
        (void)tg;
        cpa16(&XL[r * RST + off8], g_xlh + (size_t)s * 64 + off8);
    }
    // stage XR rows via shfl of this thread's tgt
    {
        int tgt2 = ei[EE + e];
#pragma unroll
        for (int i = 0; i < 8; i++) {
            int r  = i * 4 + rlane;
            int tg = __shfl_sync(0xFFFFFFFFu, tgt2, r);
            cpa16(&XR[r * RST + off8], g_xrh + (size_t)tg * 64 + off8);
        }
    }
    asm volatile("cp.async.commit_group;" ::: "memory");

    // ---- overlap: ea load + gate MLP ----
    float ea[16];
    {
        const float4* eap = (const float4*)(eag + (size_t)e * 16);
#pragma unroll
        for (int i = 0; i < 4; i++) {
            float4 v = eap[i];
            ea[4 * i + 0] = v.x; ea[4 * i + 1] = v.y;
            ea[4 * i + 2] = v.z; ea[4 * i + 3] = v.w;
        }
    }
    float gate;
    {
        u64 h2[16];
        const u64* bg1p = (const u64*)cbg1;
#pragma unroll
        for (int j = 0; j < 16; j++) h2[j] = bg1p[j];
        const u64* wg1p = (const u64*)cWg1;
#pragma unroll
        for (int i = 0; i < 16; i++) {
            u64 a2 = pack2(ea[i], ea[i]);
#pragma unroll
            for (int j = 0; j < 16; j++) fma2(h2[j], a2, wg1p[i * 16 + j]);
        }
        float gacc = cbg2[0];
#pragma unroll
        for (int j = 0; j < 16; j++) {
            float h0, h1; unpack2(h2[j], h0, h1);
            gacc += h0 * sigmoidf_(h0) * cWg2[2 * j] +
                    h1 * sigmoidf_(h1) * cWg2[2 * j + 1];
        }
        gate = sigmoidf_(gacc);
    }

    asm volatile("cp.async.wait_group 0;" ::: "memory");
    __syncwarp();

    // ---- per-head logits ----
    const u64* we2p = (const u64*)cWe;
    float ah[4];
#pragma unroll
    for (int h = 0; h < 4; h++) {
        uint4 l0 = *(const uint4*)&XL[lane * RST + h * 16];
        uint4 l1 = *(const uint4*)&XL[lane * RST + h * 16 + 8];
        uint4 r0 = *(const uint4*)&XR[lane * RST + h * 16];
        uint4 r1 = *(const uint4*)&XR[lane * RST + h * 16 + 8];

        u64 s2[8];
        {
            const unsigned* lw = (const unsigned*)&l0;
            const unsigned* rw = (const unsigned*)&r0;
#pragma unroll
            for (int p = 0; p < 4; p++) {
                __half2 sum = __hadd2(*(const __half2*)&lw[p], *(const __half2*)&rw[p]);
                float2 f = __half22float2(sum);
                s2[p] = pack2(f.x, f.y);
            }
            lw = (const unsigned*)&l1;
            rw = (const unsigned*)&r1;
#pragma unroll
            for (int p = 0; p < 4; p++) {
                __half2 sum = __hadd2(*(const __half2*)&lw[p], *(const __half2*)&rw[p]);
                float2 f = __half22float2(sum);
                s2[4 + p] = pack2(f.x, f.y);
            }
        }
#pragma unroll
        for (int i = 0; i < 16; i++) {
            u64 a2 = pack2(ea[i], ea[i]);
#pragma unroll
            for (int p = 0; p < 8; p++)
                fma2(s2[p], a2, we2p[i * 32 + h * 8 + p]);
        }
        float acc = 0.f;
#pragma unroll
        for (int p = 0; p < 8; p++) {
            float m0, m1; unpack2(s2[p], m0, m1);
            acc += leaky(m0) * catt[h * 16 + 2 * p] +
                   leaky(m1) * catt[h * 16 + 2 * p + 1];
        }
        ah[h] = __expf(acc);
    }

    g_a4[e]   = make_float4(ah[0], ah[1], ah[2], ah[3]);
    g_gate[e] = gate;
}

// ---------------------------------------------------------------------------
// Kernel: per-node gather + softmax-normalize + gate-mean + LN + SiLU + resid.
// One warp per node; lane owns channels {2c, 2c+1}. Zero atomics.
// ---------------------------------------------------------------------------
__global__ void __launch_bounds__(256) k_gather(
        const float* __restrict__ x,
        const float* __restrict__ conv_bias,
        const float* __restrict__ gamma,
        const float* __restrict__ beta,
        float* __restrict__ out) {
    int n = (blockIdx.x * blockDim.x + threadIdx.x) >> 5;
    int lane = threadIdx.x & 31;
    int h = lane >> 3;

    int row = g_off[n], end = g_off[n + 1];
    int deg = end - row;

    u64 acc = pack2(0.f, 0.f);
    float den = 0.f, gsum = 0.f;

    int2 se = (deg > 0) ? g_sed[row] : make_int2(0, 0);
    for (int j = 0; j < deg; j++) {
        float4 a4 = g_a4[se.y];
        float gt  = g_gate[se.y];
        __half2 xl2 = *(const __half2*)&g_xlh[(size_t)se.x * 64 + 2 * lane];
        int2 se_n = (j + 1 < deg) ? g_sed[row + j + 1] : se;
        float2 xf = __half22float2(xl2);
        float a = (h == 0) ? a4.x : (h == 1) ? a4.y : (h == 2) ? a4.z : a4.w;
        fma2(acc, pack2(a, a), pack2(xf.x, xf.y));
        den  += a;
        gsum += gt;
        se = se_n;
    }

    float inv = den > 0.f ? 1.f / den : 0.f;
    float mg  = gsum / fmaxf((float)deg, 1.f);

    float2 cb = ((const float2*)conv_bias)[lane];
    float a0, a1; unpack2(acc, a0, a1);
    float v0 = (a0 * inv + cb.x) * mg;
    float v1 = (a1 * inv + cb.y) * mg;

    float s  = v0 + v1;
    float sq = v0 * v0 + v1 * v1;
#pragma unroll
    for (int o = 16; o > 0; o >>= 1) {
        s  += __shfl_xor_sync(0xFFFFFFFFu, s,  o);
        sq += __shfl_xor_sync(0xFFFFFFFFu, sq, o);
    }
    float mu   = s * (1.f / 64.f);
    float var  = sq * (1.f / 64.f) - mu * mu;
    float rstd = rsqrtf(var + 1e-5f);

    float2 g  = ((const float2*)gamma)[lane];
    float2 bt = ((const float2*)beta)[lane];
    float2 xv = ((const float2*)x)[(size_t)n * 32 + lane];
    float n0 = (v0 - mu) * rstd * g.x + bt.x;
    float n1 = (v1 - mu) * rstd * g.y + bt.y;
    n0 *= sigmoidf_(n0);
    n1 *= sigmoidf_(n1);
    ((float2*)out)[(size_t)n * 32 + lane] = make_float2(n0 + xv.x, n1 + xv.y);
}

// ---------------------------------------------------------------------------
extern "C" void kernel_launch(void* const* d_in, const int* in_sizes, int n_in,
                              void* d_out, int out_size) {
    const float* x         = (const float*)d_in[0];
    const int*   ei        = (const int*)  d_in[1];
    const float* edge_attr = (const float*)d_in[2];
    const float* Wl        = (const float*)d_in[3];
    const float* bl        = (const float*)d_in[4];
    const float* Wr        = (const float*)d_in[5];
    const float* br        = (const float*)d_in[6];
    const float* conv_bias = (const float*)d_in[9];
    const float* gamma     = (const float*)d_in[14];
    const float* beta      = (const float*)d_in[15];
    float* out = (float*)d_out;

    cudaMemcpyToSymbolAsync(cWe,  d_in[7],  1024 * 4, 0, cudaMemcpyDeviceToDevice, 0);
    cudaMemcpyToSymbolAsync(catt, d_in[8],  64 * 4,   0, cudaMemcpyDeviceToDevice, 0);
    cudaMemcpyToSymbolAsync(cWg1, d_in[10], 512 * 4,  0, cudaMemcpyDeviceToDevice, 0);
    cudaMemcpyToSymbolAsync(cbg1, d_in[11], 32 * 4,   0, cudaMemcpyDeviceToDevice, 0);
    cudaMemcpyToSymbolAsync(cWg2, d_in[12], 32 * 4,   0, cudaMemcpyDeviceToDevice, 0);
    cudaMemcpyToSymbolAsync(cbg2, d_in[13], 4,        0, cudaMemcpyDeviceToDevice, 0);

    k_prep   <<<(NN + 63) / 64, 256>>>(x, Wl, bl, Wr, br);
    k_hist   <<<EE / 256, 256>>>(ei);
    k_scanA  <<<SCANB, 256>>>();
    k_scanB  <<<1, 512>>>();
    k_scanC  <<<SCANB, 256>>>();
    k_scatter<<<EE / 256, 256>>>(ei);
    k_edge   <<<EE / ETPB, ETPB>>>(ei, edge_attr);
    k_gather <<<NN * 32 / 256, 256>>>(x, conv_bias, gamma, beta, out);
}